// round 1
// baseline (speedup 1.0000x reference)
#include <cuda_runtime.h>
#include <cuda_bf16.h>
#include <cstdint>

#define RR 8
#define NN 50000
#define EE 400000
#define DD 128
#define CC 16
#define BB 4
#define RE_TOT (RR*EE)   /* 3,200,000 */
#define RN (RR*NN)       /* 400,000   */
#define NP (NN+64)       /* padded rows so GEMM tiles never fault */

// ---------------- scratch (static device globals; no allocs) ----------------
__device__ int   g_deg[RN];
__device__ int   g_off[RN];
__device__ int   g_cur[RN];
__device__ int   g_col[RE_TOT];
__device__ int   g_bsums[512];
__device__ float g_inv[RN];
__device__ float g_h  [(size_t)NP*DD];
__device__ float g_M  [(size_t)4*NP*DD];   // [b][NP][D]
__device__ float g_h1 [(size_t)NP*DD];
__device__ float g_Y  [(size_t)NP*64];
__device__ float g_Wy [DD*64];

// ---------------- degree / inv ----------------
__global__ void k_deg(const int* __restrict__ edst){
    int i = blockIdx.x*blockDim.x + threadIdx.x;
    if (i < RE_TOT){
        int r = i / EE;
        atomicAdd(&g_deg[r*NN + edst[i]], 1);
    }
}

__global__ void k_invdeg(){
    int i = blockIdx.x*blockDim.x + threadIdx.x;
    if (i < RN) g_inv[i] = 1.0f / fmaxf((float)g_deg[i], 1.0f);
}

// ---------------- hierarchical exclusive scan over g_deg -> g_off ----------------
__device__ __forceinline__ int warp_incl_scan(int v){
    int lane = threadIdx.x & 31;
    #pragma unroll
    for (int o = 1; o < 32; o <<= 1){
        int u = __shfl_up_sync(0xffffffffu, v, o);
        if (lane >= o) v += u;
    }
    return v;
}

__global__ void k_scan1(){   // 512 threads, 1024 elems/block
    __shared__ int ws[16];
    int t = threadIdx.x;
    int base = blockIdx.x*1024;
    int i0 = base + 2*t;
    int a = (i0   < RN) ? g_deg[i0]   : 0;
    int b = (i0+1 < RN) ? g_deg[i0+1] : 0;
    int s = a + b;
    int inc = warp_incl_scan(s);
    int lane = t & 31, w = t >> 5;
    if (lane == 31) ws[w] = inc;
    __syncthreads();
    if (t < 16){
        int v = ws[t];
        #pragma unroll
        for (int o = 1; o < 16; o <<= 1){
            int u = __shfl_up_sync(0x0000ffffu, v, o);
            if (t >= o) v += u;
        }
        ws[t] = v;
    }
    __syncthreads();
    int add = (w > 0) ? ws[w-1] : 0;
    int excl = add + inc - s;
    if (i0   < RN) g_off[i0]   = excl;
    if (i0+1 < RN) g_off[i0+1] = excl + a;
    if (t == 0) g_bsums[blockIdx.x] = ws[15];
}

__global__ void k_scan2(int nb){  // single block of 512
    __shared__ int ws[16];
    int t = threadIdx.x;
    int v = (t < nb) ? g_bsums[t] : 0;
    int inc = warp_incl_scan(v);
    int lane = t & 31, w = t >> 5;
    if (lane == 31) ws[w] = inc;
    __syncthreads();
    if (t < 16){
        int x = ws[t];
        #pragma unroll
        for (int o = 1; o < 16; o <<= 1){
            int u = __shfl_up_sync(0x0000ffffu, x, o);
            if (t >= o) x += u;
        }
        ws[t] = x;
    }
    __syncthreads();
    int add = (w > 0) ? ws[w-1] : 0;
    if (t < nb) g_bsums[t] = add + inc;
}

__global__ void k_scan3(){
    int i = blockIdx.x*blockDim.x + threadIdx.x;
    if (i < RN){
        int g = i >> 10;
        if (g > 0) g_off[i] += g_bsums[g-1];
    }
}

__global__ void k_fill(const int* __restrict__ esrc, const int* __restrict__ edst){
    int i = blockIdx.x*blockDim.x + threadIdx.x;
    if (i < RE_TOT){
        int r = i / EE;
        int d = edst[i];
        int pos = atomicAdd(&g_cur[r*NN + d], 1);
        g_col[pos] = esrc[i];
    }
}

// ---------------- aggregation kernels (warp per node, CSR gather) ----------------
__device__ __forceinline__ float4 ld_row4(const float* __restrict__ base, int s, int lane){
    return reinterpret_cast<const float4*>(base + (size_t)s*DD)[lane];
}

__global__ __launch_bounds__(256) void k_agg0(const float* __restrict__ embeds,
                                              const float* __restrict__ ebias){
    int n = blockIdx.x*8 + (threadIdx.x >> 5);
    if (n >= NN) return;
    int lane = threadIdx.x & 31;
    float4 tot = {0.f,0.f,0.f,0.f};
    #pragma unroll 1
    for (int r = 0; r < RR; r++){
        int rn = r*NN + n;
        int s0 = g_off[rn];
        int dg = g_deg[rn];
        const float* base = embeds + (size_t)r*NN*DD;
        float4 acc = {0.f,0.f,0.f,0.f};
        for (int bs = 0; bs < dg; bs += 32){
            int m = min(32, dg - bs);
            int cv = (lane < m) ? g_col[s0 + bs + lane] : 0;
            int j = 0;
            for (; j + 4 <= m; j += 4){
                int sa = __shfl_sync(0xffffffffu, cv, j);
                int sb = __shfl_sync(0xffffffffu, cv, j+1);
                int sc = __shfl_sync(0xffffffffu, cv, j+2);
                int sd = __shfl_sync(0xffffffffu, cv, j+3);
                float4 v0 = ld_row4(base, sa, lane);
                float4 v1 = ld_row4(base, sb, lane);
                float4 v2 = ld_row4(base, sc, lane);
                float4 v3 = ld_row4(base, sd, lane);
                acc.x += v0.x + v1.x + v2.x + v3.x;
                acc.y += v0.y + v1.y + v2.y + v3.y;
                acc.z += v0.z + v1.z + v2.z + v3.z;
                acc.w += v0.w + v1.w + v2.w + v3.w;
            }
            for (; j < m; j++){
                int s = __shfl_sync(0xffffffffu, cv, j);
                float4 v = ld_row4(base, s, lane);
                acc.x += v.x; acc.y += v.y; acc.z += v.z; acc.w += v.w;
            }
        }
        float iv = g_inv[rn];
        tot.x += acc.x*iv; tot.y += acc.y*iv; tot.z += acc.z*iv; tot.w += acc.w*iv;
    }
    float4 bb = reinterpret_cast<const float4*>(ebias)[lane];
    float4 o;
    o.x = fmaxf(tot.x + bb.x, 0.f);
    o.y = fmaxf(tot.y + bb.y, 0.f);
    o.z = fmaxf(tot.z + bb.z, 0.f);
    o.w = fmaxf(tot.w + bb.w, 0.f);
    reinterpret_cast<float4*>(g_h + (size_t)n*DD)[lane] = o;
}

__global__ __launch_bounds__(256) void k_agg1(const float* __restrict__ w1comp){
    int n = blockIdx.x*8 + (threadIdx.x >> 5);
    if (n >= NN) return;
    int lane = threadIdx.x & 31;
    float4 macc[4];
    #pragma unroll
    for (int b = 0; b < 4; b++) macc[b] = make_float4(0.f,0.f,0.f,0.f);
    #pragma unroll 1
    for (int r = 0; r < RR; r++){
        int rn = r*NN + n;
        int s0 = g_off[rn];
        int dg = g_deg[rn];
        float4 acc = {0.f,0.f,0.f,0.f};
        for (int bs = 0; bs < dg; bs += 32){
            int m = min(32, dg - bs);
            int cv = (lane < m) ? g_col[s0 + bs + lane] : 0;
            int j = 0;
            for (; j + 4 <= m; j += 4){
                int sa = __shfl_sync(0xffffffffu, cv, j);
                int sb = __shfl_sync(0xffffffffu, cv, j+1);
                int sc = __shfl_sync(0xffffffffu, cv, j+2);
                int sd = __shfl_sync(0xffffffffu, cv, j+3);
                float4 v0 = ld_row4(g_h, sa, lane);
                float4 v1 = ld_row4(g_h, sb, lane);
                float4 v2 = ld_row4(g_h, sc, lane);
                float4 v3 = ld_row4(g_h, sd, lane);
                acc.x += v0.x + v1.x + v2.x + v3.x;
                acc.y += v0.y + v1.y + v2.y + v3.y;
                acc.z += v0.z + v1.z + v2.z + v3.z;
                acc.w += v0.w + v1.w + v2.w + v3.w;
            }
            for (; j < m; j++){
                int s = __shfl_sync(0xffffffffu, cv, j);
                float4 v = ld_row4(g_h, s, lane);
                acc.x += v.x; acc.y += v.y; acc.z += v.z; acc.w += v.w;
            }
        }
        float iv = g_inv[rn];
        #pragma unroll
        for (int b = 0; b < 4; b++){
            float w = w1comp[r*BB + b] * iv;
            macc[b].x += acc.x*w; macc[b].y += acc.y*w;
            macc[b].z += acc.z*w; macc[b].w += acc.w*w;
        }
    }
    #pragma unroll
    for (int b = 0; b < 4; b++)
        reinterpret_cast<float4*>(g_M + ((size_t)b*NP + n)*DD)[lane] = macc[b];
}

// ---------------- GEMM1: h1 = relu(M[N,512] @ w1_basis[512,128] + b1) ----------------
__global__ __launch_bounds__(256) void k_gemm1(const float* __restrict__ wbasis,
                                               const float* __restrict__ b1){
    __shared__ float Ws[64*128];
    __shared__ float As[64*64];
    int t  = threadIdx.x;
    int n0 = blockIdx.x*64;
    int cg = t & 31;    // cols cg*4 .. cg*4+3
    int ng = t >> 5;    // nodes n0 + ng*8 .. +7
    float4 acc[8];
    #pragma unroll
    for (int i = 0; i < 8; i++) acc[i] = make_float4(0.f,0.f,0.f,0.f);
    for (int kt = 0; kt < 8; kt++){
        int b  = kt >> 1;
        int ds = (kt & 1)*64;
        const float* Ablk = g_M + ((size_t)b*NP + n0)*DD + ds;
        #pragma unroll
        for (int j = 0; j < 4; j++){
            int f = t + j*256; int row = f >> 4; int c4 = f & 15;
            *(float4*)&As[row*64 + c4*4] = *(const float4*)&Ablk[(size_t)row*DD + c4*4];
        }
        const float* Wblk = wbasis + (size_t)kt*64*128;
        #pragma unroll
        for (int j = 0; j < 8; j++){
            int f = t + j*256; int row = f >> 5; int c4 = f & 31;
            *(float4*)&Ws[row*128 + c4*4] = *(const float4*)&Wblk[row*128 + c4*4];
        }
        __syncthreads();
        #pragma unroll 8
        for (int kk = 0; kk < 64; kk++){
            float4 wf = *(float4*)&Ws[kk*128 + cg*4];
            #pragma unroll
            for (int i = 0; i < 8; i++){
                float a = As[(ng*8 + i)*64 + kk];
                acc[i].x += a*wf.x; acc[i].y += a*wf.y;
                acc[i].z += a*wf.z; acc[i].w += a*wf.w;
            }
        }
        __syncthreads();
    }
    float4 bb = *(const float4*)&b1[cg*4];
    #pragma unroll
    for (int i = 0; i < 8; i++){
        int n = n0 + ng*8 + i;
        float4 o;
        o.x = fmaxf(acc[i].x + bb.x, 0.f);
        o.y = fmaxf(acc[i].y + bb.y, 0.f);
        o.z = fmaxf(acc[i].z + bb.z, 0.f);
        o.w = fmaxf(acc[i].w + bb.w, 0.f);
        *(float4*)&g_h1[(size_t)n*DD + cg*4] = o;
    }
}

// ---------------- Wy prep + GEMM-Y: Y = h1[N,128] @ Wy[128,64] ----------------
__global__ void k_prepWy(const float* __restrict__ w2b){
    int tid = blockIdx.x*blockDim.x + threadIdx.x;
    if (tid < DD*BB*CC){
        int k = tid >> 6;
        int j = tid & 63;
        int b = j >> 4;
        int c = j & 15;
        g_Wy[k*64 + j] = w2b[((size_t)b*DD + k)*CC + c];
    }
}

__global__ __launch_bounds__(256) void k_gemmY(){
    __shared__ float Ws[64*64];
    __shared__ float As[64*64];
    int t  = threadIdx.x;
    int n0 = blockIdx.x*64;
    int cg = t & 15;   // cols cg*4
    int ng = t >> 4;   // nodes n0 + ng*4 .. +3
    float4 acc[4];
    #pragma unroll
    for (int i = 0; i < 4; i++) acc[i] = make_float4(0.f,0.f,0.f,0.f);
    for (int kt = 0; kt < 2; kt++){
        #pragma unroll
        for (int j = 0; j < 4; j++){
            int f = t + j*256; int row = f >> 4; int c4 = f & 15;
            *(float4*)&As[row*64 + c4*4] =
                *(const float4*)&g_h1[(size_t)(n0+row)*DD + kt*64 + c4*4];
        }
        #pragma unroll
        for (int j = 0; j < 4; j++){
            int f = t + j*256; int row = f >> 4; int c4 = f & 15;
            *(float4*)&Ws[row*64 + c4*4] = *(const float4*)&g_Wy[(kt*64+row)*64 + c4*4];
        }
        __syncthreads();
        #pragma unroll 16
        for (int kk = 0; kk < 64; kk++){
            float4 wf = *(float4*)&Ws[kk*64 + cg*4];
            #pragma unroll
            for (int i = 0; i < 4; i++){
                float a = As[(ng*4 + i)*64 + kk];
                acc[i].x += a*wf.x; acc[i].y += a*wf.y;
                acc[i].z += a*wf.z; acc[i].w += a*wf.w;
            }
        }
        __syncthreads();
    }
    #pragma unroll
    for (int i = 0; i < 4; i++){
        int n = n0 + ng*4 + i;
        *(float4*)&g_Y[(size_t)n*64 + cg*4] = acc[i];
    }
}

// ---------------- output aggregation: out = b2 + sum_r inv * agg(comb(Y)) ----------------
__global__ __launch_bounds__(256) void k_agg2(const float* __restrict__ w2comp,
                                              const float* __restrict__ b2,
                                              float* __restrict__ out){
    int n = blockIdx.x*8 + (threadIdx.x >> 5);
    if (n >= NN) return;
    int lane = threadIdx.x & 31;
    int half = lane >> 4;
    int c    = lane & 15;
    float accn = 0.f;
    #pragma unroll 1
    for (int r = 0; r < RR; r++){
        int rn = r*NN + n;
        int s0 = g_off[rn];
        int dg = g_deg[rn];
        float c0 = w2comp[r*BB+0], c1 = w2comp[r*BB+1];
        float c2 = w2comp[r*BB+2], c3 = w2comp[r*BB+3];
        float accr = 0.f;
        for (int bs = 0; bs < dg; bs += 32){
            int m = min(32, dg - bs);
            int cv = (lane < m) ? g_col[s0 + bs + lane] : 0;
            for (int jj = 0; jj < m; jj += 2){
                int j = jj + half;
                int sel = (j < m) ? j : (m - 1);
                int s = __shfl_sync(0xffffffffu, cv, sel);
                if (j < m){
                    const float* yr = g_Y + (size_t)s*64;
                    accr += c0*yr[c] + c1*yr[c+16] + c2*yr[c+32] + c3*yr[c+48];
                }
            }
        }
        accn += accr * g_inv[rn];
    }
    float oth = __shfl_xor_sync(0xffffffffu, accn, 16);
    accn += oth;
    if (half == 0) out[(size_t)n*CC + c] = accn + b2[c];
}

// ---------------- launch ----------------
extern "C" void kernel_launch(void* const* d_in, const int* in_sizes, int n_in,
                              void* d_out, int out_size){
    const int*   esrc   = (const int*)  d_in[0];
    const int*   edst   = (const int*)  d_in[1];
    const float* embeds = (const float*)d_in[2];
    const float* ebias  = (const float*)d_in[3];
    const float* w1b    = (const float*)d_in[4];
    const float* w1c    = (const float*)d_in[5];
    const float* b1     = (const float*)d_in[6];
    const float* w2b    = (const float*)d_in[7];
    const float* w2c    = (const float*)d_in[8];
    const float* b2     = (const float*)d_in[9];
    float* out = (float*)d_out;

    void *p_deg, *p_off, *p_cur;
    cudaGetSymbolAddress(&p_deg, g_deg);
    cudaGetSymbolAddress(&p_off, g_off);
    cudaGetSymbolAddress(&p_cur, g_cur);

    const int scan_blocks = (RN + 1023) / 1024;   // 391

    cudaMemsetAsync(p_deg, 0, sizeof(int)*RN);
    k_deg   <<<(RE_TOT+255)/256, 256>>>(edst);
    k_invdeg<<<(RN+255)/256, 256>>>();
    k_scan1 <<<scan_blocks, 512>>>();
    k_scan2 <<<1, 512>>>(scan_blocks);
    k_scan3 <<<(RN+255)/256, 256>>>();
    cudaMemcpyAsync(p_cur, p_off, sizeof(int)*RN, cudaMemcpyDeviceToDevice);
    k_fill  <<<(RE_TOT+255)/256, 256>>>(esrc, edst);

    k_agg0  <<<(NN+7)/8, 256>>>(embeds, ebias);
    k_agg1  <<<(NN+7)/8, 256>>>(w1c);
    k_gemm1 <<<(NN+63)/64, 256>>>(w1b, b1);
    k_prepWy<<<(DD*BB*CC+255)/256, 256>>>(w2b);
    k_gemmY <<<(NN+63)/64, 256>>>();
    k_agg2  <<<(NN+7)/8, 256>>>(w2c, b2, out);
}

// round 3
// speedup vs baseline: 1.2826x; 1.2826x over previous
#include <cuda_runtime.h>
#include <cuda_fp16.h>
#include <cstdint>

#define RR 8
#define NN 50000
#define EE 400000
#define DD 128
#define CC 16
#define BB 4
#define RE_TOT (RR*EE)   /* 3,200,000 */
#define RN (RR*NN)       /* 400,000   */
#define NP 50064         /* padded rows (>= 391*128 = 50048) */

// ---------------- scratch (static device globals; no allocs) ----------------
__device__ int    g_deg[RN];
__device__ int    g_off[RN];
__device__ int    g_cur[RN];
__device__ int    g_col[RE_TOT];
__device__ int    g_bsums[512];
__device__ float  g_inv[RN];
__device__ __half g_h  [(size_t)NP*DD];      // [NP][128]
__device__ __half g_M  [(size_t)NP*512];     // [NP][512] row-major (k = b*128 + i)
__device__ __half g_h1 [(size_t)NP*DD];      // [NP][128]
__device__ __half g_Y  [(size_t)NP*64];      // [NP][64]  (col = b*16 + c)
__device__ uint2  g_Bf1[32*16*32];           // B frags gemm1: [ks][nt][lane]
__device__ uint2  g_BfY[8*8*32];             // B frags gemmY

// ---------------- degree / inv ----------------
__global__ void k_deg(const int* __restrict__ edst){
    int i = blockIdx.x*blockDim.x + threadIdx.x;
    if (i < RE_TOT){
        int r = i / EE;
        atomicAdd(&g_deg[r*NN + edst[i]], 1);
    }
}

__global__ void k_invdeg(){
    int i = blockIdx.x*blockDim.x + threadIdx.x;
    if (i < RN) g_inv[i] = 1.0f / fmaxf((float)g_deg[i], 1.0f);
}

// ---------------- hierarchical exclusive scan over g_deg -> g_off ----------------
__device__ __forceinline__ int warp_incl_scan(int v){
    int lane = threadIdx.x & 31;
    #pragma unroll
    for (int o = 1; o < 32; o <<= 1){
        int u = __shfl_up_sync(0xffffffffu, v, o);
        if (lane >= o) v += u;
    }
    return v;
}

__global__ void k_scan1(){   // 512 threads, 1024 elems/block
    __shared__ int ws[16];
    int t = threadIdx.x;
    int base = blockIdx.x*1024;
    int i0 = base + 2*t;
    int a = (i0   < RN) ? g_deg[i0]   : 0;
    int b = (i0+1 < RN) ? g_deg[i0+1] : 0;
    int s = a + b;
    int inc = warp_incl_scan(s);
    int lane = t & 31, w = t >> 5;
    if (lane == 31) ws[w] = inc;
    __syncthreads();
    if (t < 16){
        int v = ws[t];
        #pragma unroll
        for (int o = 1; o < 16; o <<= 1){
            int u = __shfl_up_sync(0x0000ffffu, v, o);
            if (t >= o) v += u;
        }
        ws[t] = v;
    }
    __syncthreads();
    int add = (w > 0) ? ws[w-1] : 0;
    int excl = add + inc - s;
    if (i0   < RN) g_off[i0]   = excl;
    if (i0+1 < RN) g_off[i0+1] = excl + a;
    if (t == 0) g_bsums[blockIdx.x] = ws[15];
}

__global__ void k_scan2(int nb){  // single block of 512
    __shared__ int ws[16];
    int t = threadIdx.x;
    int v = (t < nb) ? g_bsums[t] : 0;
    int inc = warp_incl_scan(v);
    int lane = t & 31, w = t >> 5;
    if (lane == 31) ws[w] = inc;
    __syncthreads();
    if (t < 16){
        int x = ws[t];
        #pragma unroll
        for (int o = 1; o < 16; o <<= 1){
            int u = __shfl_up_sync(0x0000ffffu, x, o);
            if (t >= o) x += u;
        }
        ws[t] = x;
    }
    __syncthreads();
    int add = (w > 0) ? ws[w-1] : 0;
    if (t < nb) g_bsums[t] = add + inc;
}

__global__ void k_scan3(){
    int i = blockIdx.x*blockDim.x + threadIdx.x;
    if (i < RN){
        int g = i >> 10;
        if (g > 0) g_off[i] += g_bsums[g-1];
    }
}

__global__ void k_fill(const int* __restrict__ esrc, const int* __restrict__ edst){
    int i = blockIdx.x*blockDim.x + threadIdx.x;
    if (i < RE_TOT){
        int r = i / EE;
        int d = edst[i];
        int pos = atomicAdd(&g_cur[r*NN + d], 1);
        g_col[pos] = esrc[i];
    }
}

// ---------------- agg0: warp per node, gather fp32 embeds, write h fp16 ----------------
__device__ __forceinline__ float4 ld_row4(const float* __restrict__ base, int s, int lane){
    return reinterpret_cast<const float4*>(base + (size_t)s*DD)[lane];
}

__global__ __launch_bounds__(256) void k_agg0(const float* __restrict__ embeds,
                                              const float* __restrict__ ebias){
    int n = blockIdx.x*8 + (threadIdx.x >> 5);
    if (n >= NN) return;
    int lane = threadIdx.x & 31;
    float4 tot = {0.f,0.f,0.f,0.f};
    #pragma unroll 1
    for (int r = 0; r < RR; r++){
        int rn = r*NN + n;
        int s0 = g_off[rn];
        int dg = g_deg[rn];
        const float* base = embeds + (size_t)r*NN*DD;
        float4 acc = {0.f,0.f,0.f,0.f};
        for (int bs = 0; bs < dg; bs += 32){
            int m = min(32, dg - bs);
            int cv = (lane < m) ? g_col[s0 + bs + lane] : 0;
            int j = 0;
            for (; j + 4 <= m; j += 4){
                int sa = __shfl_sync(0xffffffffu, cv, j);
                int sb = __shfl_sync(0xffffffffu, cv, j+1);
                int sc = __shfl_sync(0xffffffffu, cv, j+2);
                int sd = __shfl_sync(0xffffffffu, cv, j+3);
                float4 v0 = ld_row4(base, sa, lane);
                float4 v1 = ld_row4(base, sb, lane);
                float4 v2 = ld_row4(base, sc, lane);
                float4 v3 = ld_row4(base, sd, lane);
                acc.x += v0.x + v1.x + v2.x + v3.x;
                acc.y += v0.y + v1.y + v2.y + v3.y;
                acc.z += v0.z + v1.z + v2.z + v3.z;
                acc.w += v0.w + v1.w + v2.w + v3.w;
            }
            for (; j < m; j++){
                int s = __shfl_sync(0xffffffffu, cv, j);
                float4 v = ld_row4(base, s, lane);
                acc.x += v.x; acc.y += v.y; acc.z += v.z; acc.w += v.w;
            }
        }
        float iv = g_inv[rn];
        tot.x += acc.x*iv; tot.y += acc.y*iv; tot.z += acc.z*iv; tot.w += acc.w*iv;
    }
    float4 bb = reinterpret_cast<const float4*>(ebias)[lane];
    __half2 p0 = __floats2half2_rn(fmaxf(tot.x + bb.x, 0.f), fmaxf(tot.y + bb.y, 0.f));
    __half2 p1 = __floats2half2_rn(fmaxf(tot.z + bb.z, 0.f), fmaxf(tot.w + bb.w, 0.f));
    uint2 st; st.x = *(uint32_t*)&p0; st.y = *(uint32_t*)&p1;
    reinterpret_cast<uint2*>(g_h + (size_t)n*DD)[lane] = st;
}

// ---------------- agg1: gather h fp16, per-basis combine, write M fp16 ----------------
__global__ __launch_bounds__(256) void k_agg1(const float* __restrict__ w1comp){
    int n = blockIdx.x*8 + (threadIdx.x >> 5);
    if (n >= NN) return;
    int lane = threadIdx.x & 31;
    float4 macc[4];
    #pragma unroll
    for (int b = 0; b < 4; b++) macc[b] = make_float4(0.f,0.f,0.f,0.f);
    #pragma unroll 1
    for (int r = 0; r < RR; r++){
        int rn = r*NN + n;
        int s0 = g_off[rn];
        int dg = g_deg[rn];
        float4 acc = {0.f,0.f,0.f,0.f};
        for (int bs = 0; bs < dg; bs += 32){
            int m = min(32, dg - bs);
            int cv = (lane < m) ? g_col[s0 + bs + lane] : 0;
            int j = 0;
            for (; j + 4 <= m; j += 4){
                int sa = __shfl_sync(0xffffffffu, cv, j);
                int sb = __shfl_sync(0xffffffffu, cv, j+1);
                int sc = __shfl_sync(0xffffffffu, cv, j+2);
                int sd = __shfl_sync(0xffffffffu, cv, j+3);
                uint2 v0 = reinterpret_cast<const uint2*>(g_h + (size_t)sa*DD)[lane];
                uint2 v1 = reinterpret_cast<const uint2*>(g_h + (size_t)sb*DD)[lane];
                uint2 v2 = reinterpret_cast<const uint2*>(g_h + (size_t)sc*DD)[lane];
                uint2 v3 = reinterpret_cast<const uint2*>(g_h + (size_t)sd*DD)[lane];
                float2 a0 = __half22float2(*(__half2*)&v0.x), b0 = __half22float2(*(__half2*)&v0.y);
                float2 a1 = __half22float2(*(__half2*)&v1.x), b1 = __half22float2(*(__half2*)&v1.y);
                float2 a2 = __half22float2(*(__half2*)&v2.x), b2 = __half22float2(*(__half2*)&v2.y);
                float2 a3 = __half22float2(*(__half2*)&v3.x), b3 = __half22float2(*(__half2*)&v3.y);
                acc.x += a0.x + a1.x + a2.x + a3.x;
                acc.y += a0.y + a1.y + a2.y + a3.y;
                acc.z += b0.x + b1.x + b2.x + b3.x;
                acc.w += b0.y + b1.y + b2.y + b3.y;
            }
            for (; j < m; j++){
                int s = __shfl_sync(0xffffffffu, cv, j);
                uint2 v = reinterpret_cast<const uint2*>(g_h + (size_t)s*DD)[lane];
                float2 a = __half22float2(*(__half2*)&v.x), b = __half22float2(*(__half2*)&v.y);
                acc.x += a.x; acc.y += a.y; acc.z += b.x; acc.w += b.y;
            }
        }
        float iv = g_inv[rn];
        #pragma unroll
        for (int b = 0; b < 4; b++){
            float w = w1comp[r*BB + b] * iv;
            macc[b].x += acc.x*w; macc[b].y += acc.y*w;
            macc[b].z += acc.z*w; macc[b].w += acc.w*w;
        }
    }
    #pragma unroll
    for (int b = 0; b < 4; b++){
        __half2 p0 = __floats2half2_rn(macc[b].x, macc[b].y);
        __half2 p1 = __floats2half2_rn(macc[b].z, macc[b].w);
        uint2 st; st.x = *(uint32_t*)&p0; st.y = *(uint32_t*)&p1;
        *reinterpret_cast<uint2*>(g_M + (size_t)n*512 + b*128 + lane*4) = st;
    }
}

// ---------------- B-fragment prep (fp32 -> fp16 mma fragment layout) ----------------
__device__ __forceinline__ uint32_t pk(float a, float b){
    __half2 h = __floats2half2_rn(a, b);
    return *(uint32_t*)&h;
}

__global__ void k_prepB1(const float* __restrict__ w1b){
    int i = blockIdx.x*blockDim.x + threadIdx.x;      // [ks(32)][nt(16)][lane(32)]
    if (i >= 32*16*32) return;
    int lane = i & 31, nt = (i >> 5) & 15, ks = i >> 9;
    int k0 = ks*16 + (lane & 3)*2;
    int n  = nt*8 + (lane >> 2);
    uint2 v;
    v.x = pk(w1b[(size_t)k0*128 + n],     w1b[(size_t)(k0+1)*128 + n]);
    v.y = pk(w1b[(size_t)(k0+8)*128 + n], w1b[(size_t)(k0+9)*128 + n]);
    g_Bf1[i] = v;
}

__global__ void k_prepBY(const float* __restrict__ w2b){
    int i = blockIdx.x*blockDim.x + threadIdx.x;      // [ks(8)][nt(8)][lane(32)]
    if (i >= 8*8*32) return;
    int lane = i & 31, nt = (i >> 5) & 7, ks = i >> 8;
    int k0 = ks*16 + (lane & 3)*2;
    int n  = nt*8 + (lane >> 2);
    int b = n >> 4, c = n & 15;
    uint2 v;
    v.x = pk(w2b[((size_t)b*128 + k0)*16 + c],     w2b[((size_t)b*128 + k0+1)*16 + c]);
    v.y = pk(w2b[((size_t)b*128 + k0+8)*16 + c],   w2b[((size_t)b*128 + k0+9)*16 + c]);
    g_BfY[i] = v;
}

// ---------------- HMMA GEMM: C[128 rows/block] = A[.,KDIM] @ B[KDIM,NCOLS] ----------------
// A row-major fp16 (stride KDIM), B pre-packed fragments (LDG, L1-resident),
// C fp16 (stride NCOLS). N processed in 64-col passes => only 32 live accums.
template<int KDIM, int NCOLS, bool BIASRELU>
__global__ __launch_bounds__(256) void k_hmma(const __half* __restrict__ A,
                                              const uint2*  __restrict__ Bf,
                                              const float*  __restrict__ bias,
                                              __half* __restrict__ Cout){
    constexpr int NTT = NCOLS/8;     // total 8-col tiles
    constexpr int NH  = NCOLS/64;    // 64-col passes
    constexpr int KS  = KDIM/16;
    int t = threadIdx.x;
    int lane = t & 31, w = t >> 5;
    int mrow = blockIdx.x*128 + w*16 + (lane >> 2);
    const __half* Arow0 = A + (size_t)mrow*KDIM;
    const __half* Arow1 = Arow0 + 8*KDIM;
    int klane = (lane & 3)*2;

    #pragma unroll 1
    for (int nh = 0; nh < NH; nh++){
        float c[8][4];
        #pragma unroll
        for (int nt = 0; nt < 8; nt++){ c[nt][0]=0.f; c[nt][1]=0.f; c[nt][2]=0.f; c[nt][3]=0.f; }
        #pragma unroll 4
        for (int ks = 0; ks < KS; ks++){
            int k0 = ks*16 + klane;
            uint32_t a0 = *(const uint32_t*)(Arow0 + k0);
            uint32_t a1 = *(const uint32_t*)(Arow1 + k0);
            uint32_t a2 = *(const uint32_t*)(Arow0 + k0 + 8);
            uint32_t a3 = *(const uint32_t*)(Arow1 + k0 + 8);
            const uint2* brow = Bf + ((size_t)ks*NTT + nh*8)*32 + lane;
            #pragma unroll
            for (int nt = 0; nt < 8; nt++){
                uint2 b = brow[nt*32];
                asm volatile(
                    "mma.sync.aligned.m16n8k16.row.col.f32.f16.f16.f32 "
                    "{%0,%1,%2,%3},{%4,%5,%6,%7},{%8,%9},{%0,%1,%2,%3};\n"
                    : "+f"(c[nt][0]), "+f"(c[nt][1]), "+f"(c[nt][2]), "+f"(c[nt][3])
                    : "r"(a0), "r"(a1), "r"(a2), "r"(a3), "r"(b.x), "r"(b.y));
            }
        }
        #pragma unroll
        for (int nt = 0; nt < 8; nt++){
            int col = nh*64 + nt*8 + (lane & 3)*2;
            float v0 = c[nt][0], v1 = c[nt][1], v2 = c[nt][2], v3 = c[nt][3];
            if (BIASRELU){
                float bx = bias[col], by = bias[col+1];
                v0 = fmaxf(v0 + bx, 0.f); v1 = fmaxf(v1 + by, 0.f);
                v2 = fmaxf(v2 + bx, 0.f); v3 = fmaxf(v3 + by, 0.f);
            }
            *(__half2*)(Cout + (size_t)mrow*NCOLS + col)     = __floats2half2_rn(v0, v1);
            *(__half2*)(Cout + (size_t)(mrow+8)*NCOLS + col) = __floats2half2_rn(v2, v3);
        }
    }
}

// ---------------- output aggregation: out = b2 + sum_r inv * agg(comb(Y)) ----------------
__global__ __launch_bounds__(256) void k_agg2(const float* __restrict__ w2comp,
                                              const float* __restrict__ b2,
                                              float* __restrict__ out){
    int n = blockIdx.x*8 + (threadIdx.x >> 5);
    if (n >= NN) return;
    int lane = threadIdx.x & 31;
    int half = lane >> 4;
    int c    = lane & 15;
    float accn = 0.f;
    #pragma unroll 1
    for (int r = 0; r < RR; r++){
        int rn = r*NN + n;
        int s0 = g_off[rn];
        int dg = g_deg[rn];
        float c0 = w2comp[r*BB+0], c1 = w2comp[r*BB+1];
        float c2 = w2comp[r*BB+2], c3 = w2comp[r*BB+3];
        float accr = 0.f;
        for (int bs = 0; bs < dg; bs += 32){
            int m = min(32, dg - bs);
            int cv = (lane < m) ? g_col[s0 + bs + lane] : 0;
            for (int jj = 0; jj < m; jj += 2){
                int j = jj + half;
                int sel = (j < m) ? j : (m - 1);
                int s = __shfl_sync(0xffffffffu, cv, sel);
                if (j < m){
                    const __half* yr = g_Y + (size_t)s*64;
                    accr += c0*__half2float(yr[c])    + c1*__half2float(yr[c+16])
                          + c2*__half2float(yr[c+32]) + c3*__half2float(yr[c+48]);
                }
            }
        }
        accn += accr * g_inv[rn];
    }
    float oth = __shfl_xor_sync(0xffffffffu, accn, 16);
    accn += oth;
    if (half == 0) out[(size_t)n*CC + c] = accn + b2[c];
}

// ---------------- launch ----------------
extern "C" void kernel_launch(void* const* d_in, const int* in_sizes, int n_in,
                              void* d_out, int out_size){
    const int*   esrc   = (const int*)  d_in[0];
    const int*   edst   = (const int*)  d_in[1];
    const float* embeds = (const float*)d_in[2];
    const float* ebias  = (const float*)d_in[3];
    const float* w1b    = (const float*)d_in[4];
    const float* w1c    = (const float*)d_in[5];
    const float* b1     = (const float*)d_in[6];
    const float* w2b    = (const float*)d_in[7];
    const float* w2c    = (const float*)d_in[8];
    const float* b2     = (const float*)d_in[9];
    float* out = (float*)d_out;

    void *p_deg, *p_off, *p_cur, *p_M, *p_h1, *p_Y, *p_Bf1, *p_BfY;
    cudaGetSymbolAddress(&p_deg, g_deg);
    cudaGetSymbolAddress(&p_off, g_off);
    cudaGetSymbolAddress(&p_cur, g_cur);
    cudaGetSymbolAddress(&p_M,   g_M);
    cudaGetSymbolAddress(&p_h1,  g_h1);
    cudaGetSymbolAddress(&p_Y,   g_Y);
    cudaGetSymbolAddress(&p_Bf1, g_Bf1);
    cudaGetSymbolAddress(&p_BfY, g_BfY);

    const int scan_blocks = (RN + 1023) / 1024;   // 391

    cudaMemsetAsync(p_deg, 0, sizeof(int)*RN);
    k_deg   <<<(RE_TOT+255)/256, 256>>>(edst);
    k_invdeg<<<(RN+255)/256, 256>>>();
    k_scan1 <<<scan_blocks, 512>>>();
    k_scan2 <<<1, 512>>>(scan_blocks);
    k_scan3 <<<(RN+255)/256, 256>>>();
    cudaMemcpyAsync(p_cur, p_off, sizeof(int)*RN, cudaMemcpyDeviceToDevice);
    k_fill  <<<(RE_TOT+255)/256, 256>>>(esrc, edst);

    k_prepB1<<<(32*16*32+255)/256, 256>>>(w1b);
    k_prepBY<<<(8*8*32+255)/256, 256>>>(w2b);

    k_agg0  <<<(NN+7)/8, 256>>>(embeds, ebias);
    k_agg1  <<<(NN+7)/8, 256>>>(w1c);
    k_hmma<512,128,true ><<<391, 256>>>((const __half*)p_M,  (const uint2*)p_Bf1, b1,
                                        (__half*)p_h1);
    k_hmma<128, 64,false><<<391, 256>>>((const __half*)p_h1, (const uint2*)p_BfY, nullptr,
                                        (__half*)p_Y);
    k_agg2  <<<(NN+7)/8, 256>>>(w2c, b2, out);
}